// round 1
// baseline (speedup 1.0000x reference)
#include <cuda_runtime.h>
#include <cuda_bf16.h>
#include <math.h>

#define DIMV 1024
#define HEADS 16
#define HD 64
#define BATCH 4
#define SQ 1024
#define SK 2048

// Scratch (allocation-free rule: __device__ globals)
__device__ float g_Q[BATCH * HEADS * SQ * HD];   // [B,H,Sq,Dh]
__device__ float g_K[BATCH * HEADS * SK * HD];   // [B,H,Sk,Dh] (concat layout)
__device__ float g_V[BATCH * HEADS * SK * HD];   // [B,H,Sk,Dh]
__device__ float g_AO[BATCH * SQ * DIMV];        // [B*Sq, DIM] attention output

// ---------------------------------------------------------------------------
// GEMM: C[M,N] = A[M,K] @ W[N,K]^T + bias[N]
// mode 0: out row-major [M,N]
// mode 1: out Q head layout  [B,H,Sq,Dh]
// mode 2: out KV head layout [B,H,Sk,Dh] with sequence offset s_off
// ---------------------------------------------------------------------------
__global__ __launch_bounds__(256, 2)
void gemm_bias_kernel(const float* __restrict__ A,
                      const float* __restrict__ W,
                      const float* __restrict__ bias,
                      float* __restrict__ out,
                      int M, int N, int K, int mode, int s_off)
{
    __shared__ float As[16][128 + 4];
    __shared__ float Ws[16][128 + 4];

    const int bm = blockIdx.y * 128;
    const int bn = blockIdx.x * 128;
    const int tid = threadIdx.x;
    const int tm = (tid >> 4) << 3;   // 0..120
    const int tn = (tid & 15) << 3;   // 0..120
    const int lr = tid >> 2;          // 0..63
    const int lk = (tid & 3) << 2;    // 0,4,8,12

    float acc[8][8];
#pragma unroll
    for (int i = 0; i < 8; i++)
#pragma unroll
        for (int j = 0; j < 8; j++) acc[i][j] = 0.f;

    const float* Ag = A + (size_t)(bm + lr) * K + lk;
    const float* Wg = W + (size_t)(bn + lr) * K + lk;

    for (int k0 = 0; k0 < K; k0 += 16) {
        float4 a0 = *(const float4*)(Ag + k0);
        float4 a1 = *(const float4*)(Ag + (size_t)64 * K + k0);
        float4 w0 = *(const float4*)(Wg + k0);
        float4 w1 = *(const float4*)(Wg + (size_t)64 * K + k0);

        As[lk + 0][lr] = a0.x; As[lk + 1][lr] = a0.y;
        As[lk + 2][lr] = a0.z; As[lk + 3][lr] = a0.w;
        As[lk + 0][lr + 64] = a1.x; As[lk + 1][lr + 64] = a1.y;
        As[lk + 2][lr + 64] = a1.z; As[lk + 3][lr + 64] = a1.w;
        Ws[lk + 0][lr] = w0.x; Ws[lk + 1][lr] = w0.y;
        Ws[lk + 2][lr] = w0.z; Ws[lk + 3][lr] = w0.w;
        Ws[lk + 0][lr + 64] = w1.x; Ws[lk + 1][lr + 64] = w1.y;
        Ws[lk + 2][lr + 64] = w1.z; Ws[lk + 3][lr + 64] = w1.w;

        __syncthreads();

#pragma unroll
        for (int k = 0; k < 16; k++) {
            float a[8], b8[8];
            float4 av0 = *(const float4*)&As[k][tm];
            float4 av1 = *(const float4*)&As[k][tm + 4];
            float4 bv0 = *(const float4*)&Ws[k][tn];
            float4 bv1 = *(const float4*)&Ws[k][tn + 4];
            a[0] = av0.x; a[1] = av0.y; a[2] = av0.z; a[3] = av0.w;
            a[4] = av1.x; a[5] = av1.y; a[6] = av1.z; a[7] = av1.w;
            b8[0] = bv0.x; b8[1] = bv0.y; b8[2] = bv0.z; b8[3] = bv0.w;
            b8[4] = bv1.x; b8[5] = bv1.y; b8[6] = bv1.z; b8[7] = bv1.w;
#pragma unroll
            for (int i = 0; i < 8; i++)
#pragma unroll
                for (int j = 0; j < 8; j++)
                    acc[i][j] += a[i] * b8[j];
        }
        __syncthreads();
    }

    // Epilogue: bias + layout scatter
#pragma unroll
    for (int i = 0; i < 8; i++) {
        int row = bm + tm + i;
#pragma unroll
        for (int j = 0; j < 8; j++) {
            int col = bn + tn + j;
            float v = acc[i][j] + bias[col];
            size_t idx;
            if (mode == 0) {
                idx = (size_t)row * N + col;
            } else {
                int b = row >> 10;      // Sx = 1024
                int s = row & 1023;
                int h = col >> 6;       // Dh = 64
                int d = col & 63;
                int S = (mode == 1) ? SQ : SK;
                idx = ((size_t)(b * HEADS + h) * S + (s + s_off)) * HD + d;
            }
            out[idx] = v;
        }
    }
}

// ---------------------------------------------------------------------------
// Flash attention: grid (Sq/32, H, B), 256 threads.
// Thread t handles query row i = t>>3, output dims d in [ (t&7)*8, +8 ).
// Q row in registers; K/V tiles of 64 share one smem buffer; P in smem.
// ---------------------------------------------------------------------------
__global__ __launch_bounds__(256, 2)
void attn_kernel(const float* __restrict__ Q, const float* __restrict__ K,
                 const float* __restrict__ V, float* __restrict__ AO)
{
    __shared__ float KVs[64][68];   // padded: stride 68 floats (16B aligned rows)
    __shared__ float Ps[32][68];

    const int b = blockIdx.z, h = blockIdx.y;
    const int q0 = blockIdx.x * 32;
    const int tid = threadIdx.x;
    const int i = tid >> 3;     // query row 0..31
    const int l8 = tid & 7;     // 8-lane group id

    // Q row -> 64 registers
    const float4* Qrow = (const float4*)(Q + ((size_t)(b * HEADS + h) * SQ + q0 + i) * HD);
    float qreg[64];
#pragma unroll
    for (int c = 0; c < 16; c++) {
        float4 v = Qrow[c];
        qreg[4 * c + 0] = v.x; qreg[4 * c + 1] = v.y;
        qreg[4 * c + 2] = v.z; qreg[4 * c + 3] = v.w;
    }

    const float* Kb = K + (size_t)(b * HEADS + h) * SK * HD;
    const float* Vb = V + (size_t)(b * HEADS + h) * SK * HD;

    float m_i = -1e30f, l_i = 0.f;
    float o[8];
#pragma unroll
    for (int d = 0; d < 8; d++) o[d] = 0.f;

    for (int kt = 0; kt < SK; kt += 64) {
        __syncthreads();   // previous iteration done with KVs/Ps
        // Load K tile [64,64]
        for (int t = tid; t < 1024; t += 256) {
            int r = t >> 4, c = t & 15;
            ((float4*)KVs[r])[c] = ((const float4*)(Kb + (size_t)(kt + r) * HD))[c];
        }
        __syncthreads();

        // S = Q K^T * scale  (8 scores per thread: j = l8 + 8*jj)
        float s[8];
#pragma unroll
        for (int jj = 0; jj < 8; jj++) {
            const float4* kr = (const float4*)KVs[l8 + jj * 8];
            float dot = 0.f;
#pragma unroll
            for (int c = 0; c < 16; c++) {
                float4 kv = kr[c];
                dot += qreg[4 * c + 0] * kv.x + qreg[4 * c + 1] * kv.y
                     + qreg[4 * c + 2] * kv.z + qreg[4 * c + 3] * kv.w;
            }
            s[jj] = dot * 0.125f;  // 1/sqrt(64)
        }

        // Online softmax over the tile (reduce across the 8-lane row group)
        float tmax = s[0];
#pragma unroll
        for (int jj = 1; jj < 8; jj++) tmax = fmaxf(tmax, s[jj]);
#pragma unroll
        for (int off = 4; off >= 1; off >>= 1)
            tmax = fmaxf(tmax, __shfl_xor_sync(0xffffffffu, tmax, off));

        float newm = fmaxf(m_i, tmax);
        float corr = __expf(m_i - newm);
        float rsum = 0.f;
#pragma unroll
        for (int jj = 0; jj < 8; jj++) {
            float p = __expf(s[jj] - newm);
            Ps[i][l8 + jj * 8] = p;
            rsum += p;
        }
#pragma unroll
        for (int off = 4; off >= 1; off >>= 1)
            rsum += __shfl_xor_sync(0xffffffffu, rsum, off);

        l_i = l_i * corr + rsum;
        m_i = newm;
#pragma unroll
        for (int d = 0; d < 8; d++) o[d] *= corr;

        __syncthreads();   // K reads done, Ps visible
        // Load V tile into same buffer
        for (int t = tid; t < 1024; t += 256) {
            int r = t >> 4, c = t & 15;
            ((float4*)KVs[r])[c] = ((const float4*)(Vb + (size_t)(kt + r) * HD))[c];
        }
        __syncthreads();

        // O += P V   (thread owns d = l8*8 .. l8*8+7)
#pragma unroll
        for (int j4 = 0; j4 < 16; j4++) {
            float4 p4 = ((const float4*)Ps[i])[j4];
#pragma unroll
            for (int u = 0; u < 4; u++) {
                float p = (u == 0) ? p4.x : (u == 1) ? p4.y : (u == 2) ? p4.z : p4.w;
                const float4* vr = (const float4*)&KVs[j4 * 4 + u][l8 * 8];
                float4 v0 = vr[0], v1 = vr[1];
                o[0] += p * v0.x; o[1] += p * v0.y; o[2] += p * v0.z; o[3] += p * v0.w;
                o[4] += p * v1.x; o[5] += p * v1.y; o[6] += p * v1.z; o[7] += p * v1.w;
            }
        }
    }

    // Write O back in [B*Sq, DIM] layout (undo head split)
    float inv = 1.f / l_i;
    float* orow = AO + ((size_t)(b * SQ + q0 + i)) * DIMV + h * HD + l8 * 8;
    float4 r0 = make_float4(o[0] * inv, o[1] * inv, o[2] * inv, o[3] * inv);
    float4 r1 = make_float4(o[4] * inv, o[5] * inv, o[6] * inv, o[7] * inv);
    ((float4*)orow)[0] = r0;
    ((float4*)orow)[1] = r1;
}

// ---------------------------------------------------------------------------
extern "C" void kernel_launch(void* const* d_in, const int* in_sizes, int n_in,
                              void* d_out, int out_size)
{
    (void)in_sizes; (void)n_in; (void)out_size;
    const float* x     = (const float*)d_in[0];
    const float* y     = (const float*)d_in[1];
    const float* W_Kx  = (const float*)d_in[2];
    const float* b_Kx  = (const float*)d_in[3];
    const float* W_Qx  = (const float*)d_in[4];
    const float* b_Qx  = (const float*)d_in[5];
    const float* W_Vx  = (const float*)d_in[6];
    const float* b_Vx  = (const float*)d_in[7];
    const float* W_Ky  = (const float*)d_in[8];
    const float* b_Ky  = (const float*)d_in[9];
    const float* W_Vy  = (const float*)d_in[10];
    const float* b_Vy  = (const float*)d_in[11];
    const float* W_out = (const float*)d_in[12];
    const float* b_out = (const float*)d_in[13];
    float* out = (float*)d_out;

    void *pQ, *pK, *pV, *pAO;
    cudaGetSymbolAddress(&pQ, g_Q);
    cudaGetSymbolAddress(&pK, g_K);
    cudaGetSymbolAddress(&pV, g_V);
    cudaGetSymbolAddress(&pAO, g_AO);
    float* Qp  = (float*)pQ;
    float* Kp  = (float*)pK;
    float* Vp  = (float*)pV;
    float* AOp = (float*)pAO;

    const int M = BATCH * SQ;   // 4096
    const int N = DIMV;         // 1024
    const int Kdim = DIMV;      // 1024
    dim3 gg(N / 128, M / 128);  // (8, 32)

    // Projections (epilogue scatters into head layouts; K/V concat built in place)
    gemm_bias_kernel<<<gg, 256>>>(x, W_Qx, b_Qx, Qp, M, N, Kdim, 1, 0);
    gemm_bias_kernel<<<gg, 256>>>(x, W_Kx, b_Kx, Kp, M, N, Kdim, 2, 0);
    gemm_bias_kernel<<<gg, 256>>>(x, W_Vx, b_Vx, Vp, M, N, Kdim, 2, 0);
    gemm_bias_kernel<<<gg, 256>>>(y, W_Ky, b_Ky, Kp, M, N, Kdim, 2, SQ);
    gemm_bias_kernel<<<gg, 256>>>(y, W_Vy, b_Vy, Vp, M, N, Kdim, 2, SQ);

    // Attention
    attn_kernel<<<dim3(SQ / 32, HEADS, BATCH), 256>>>(Qp, Kp, Vp, AOp);

    // Output projection
    gemm_bias_kernel<<<gg, 256>>>(AOp, W_out, b_out, out, M, N, Kdim, 0, 0);
}

// round 2
// speedup vs baseline: 4.8989x; 4.8989x over previous
#include <cuda_runtime.h>
#include <cstdint>
#include <math.h>

#define DIMV 1024
#define HEADS 16
#define HD 64
#define BATCH 4
#define SQ 1024
#define SKTOT 2048

// Scratch (allocation-free rule: __device__ globals)
__device__ float g_Q[BATCH * HEADS * SQ * HD];     // [B,H,Sq,Dh]
__device__ float g_K[BATCH * HEADS * SKTOT * HD];  // [B,H,Sk,Dh] concat
__device__ float g_V[BATCH * HEADS * SKTOT * HD];  // [B,H,Sk,Dh]
__device__ float g_AO[BATCH * SQ * DIMV];          // [B*Sq, DIM]

// ---------------- tf32 / mma helpers ----------------
__device__ __forceinline__ uint32_t f2tf32(float x) {
    uint32_t u; asm("cvt.rna.tf32.f32 %0, %1;" : "=r"(u) : "f"(x)); return u;
}
__device__ __forceinline__ float f2tf32f(float x) { return __uint_as_float(f2tf32(x)); }

__device__ __forceinline__ uint32_t smem_u32(const void* p) {
    return (uint32_t)__cvta_generic_to_shared(p);
}
__device__ __forceinline__ void ldm_x4(uint32_t* r, uint32_t a) {
    asm volatile("ldmatrix.sync.aligned.m8n8.x4.shared.b16 {%0,%1,%2,%3}, [%4];"
                 : "=r"(r[0]), "=r"(r[1]), "=r"(r[2]), "=r"(r[3]) : "r"(a));
}
__device__ __forceinline__ void ldm_x2(uint32_t* r, uint32_t a) {
    asm volatile("ldmatrix.sync.aligned.m8n8.x2.shared.b16 {%0,%1}, [%2];"
                 : "=r"(r[0]), "=r"(r[1]) : "r"(a));
}
// D = A(16x8) * B(8x8) + D, tf32 inputs, f32 accum
__device__ __forceinline__ void mma_tf32(float* c, const uint32_t* a, const uint32_t* b) {
    asm volatile(
        "mma.sync.aligned.m16n8k8.row.col.f32.tf32.tf32.f32 "
        "{%0,%1,%2,%3},{%4,%5,%6,%7},{%8,%9},{%0,%1,%2,%3};"
        : "+f"(c[0]), "+f"(c[1]), "+f"(c[2]), "+f"(c[3])
        : "r"(a[0]), "r"(a[1]), "r"(a[2]), "r"(a[3]), "r"(b[0]), "r"(b[1]));
}

// ---------------------------------------------------------------------------
// GEMM: C[M,N] = A[M,K] @ W[N,K]^T + bias[N]   (tf32 tensor cores)
// mode 0: row-major [M,N]; mode 1: Q head layout; mode 2: KV head layout +s_off
// ---------------------------------------------------------------------------
#define GST 20   // smem row stride (floats): conflict-free ldmatrix, 16B aligned

__device__ __forceinline__ void store_pair(float* __restrict__ out, int mode, int s_off,
                                           int N, int row, int col, float v0, float v1) {
    size_t idx;
    if (mode == 0) {
        idx = (size_t)row * N + col;
    } else {
        int b = row >> 10, s = row & 1023, h = col >> 6, d = col & 63;
        int S = (mode == 1) ? SQ : SKTOT;
        idx = ((size_t)(b * HEADS + h) * S + (s + s_off)) * HD + d;
    }
    *(float2*)(out + idx) = make_float2(v0, v1);
}

__global__ __launch_bounds__(256)
void gemm_tc(const float* __restrict__ A, const float* __restrict__ W,
             const float* __restrict__ bias, float* __restrict__ out,
             int M, int N, int K, int mode, int s_off)
{
    __shared__ float As[128 * GST];
    __shared__ float Ws[128 * GST];

    const int tid = threadIdx.x;
    const int lane = tid & 31, warp = tid >> 5;
    const int wm = (warp >> 2) * 64, wn = (warp & 3) * 32;
    const int bm = blockIdx.y * 128, bn = blockIdx.x * 128;

    // staging: thread -> (row sr, k-chunk sc), rows sr and sr+64
    const int sr = tid >> 2, sc = (tid & 3) << 2;
    const float* Ag = A + (size_t)(bm + sr) * K + sc;
    const float* Wg = W + (size_t)(bn + sr) * K + sc;

    float4 pa0 = *(const float4*)Ag;
    float4 pa1 = *(const float4*)(Ag + (size_t)64 * K);
    float4 pw0 = *(const float4*)Wg;
    float4 pw1 = *(const float4*)(Wg + (size_t)64 * K);

    float acc[4][4][4];
#pragma unroll
    for (int i = 0; i < 4; i++)
#pragma unroll
        for (int j = 0; j < 4; j++)
#pragma unroll
            for (int v = 0; v < 4; v++) acc[i][j][v] = 0.f;

    const int arow = (lane < 16) ? lane : lane - 16;
    const int acol = (lane < 16) ? 0 : 4;
    const int l16 = lane & 15;
    const int brow = l16 & 7;
    const int bcol = (l16 >> 3) << 2;

    int k0 = 0;
    for (;;) {
        // store staged tile (tf32 converted)
        float4 t;
        t.x = f2tf32f(pa0.x); t.y = f2tf32f(pa0.y); t.z = f2tf32f(pa0.z); t.w = f2tf32f(pa0.w);
        *(float4*)&As[sr * GST + sc] = t;
        t.x = f2tf32f(pa1.x); t.y = f2tf32f(pa1.y); t.z = f2tf32f(pa1.z); t.w = f2tf32f(pa1.w);
        *(float4*)&As[(sr + 64) * GST + sc] = t;
        t.x = f2tf32f(pw0.x); t.y = f2tf32f(pw0.y); t.z = f2tf32f(pw0.z); t.w = f2tf32f(pw0.w);
        *(float4*)&Ws[sr * GST + sc] = t;
        t.x = f2tf32f(pw1.x); t.y = f2tf32f(pw1.y); t.z = f2tf32f(pw1.z); t.w = f2tf32f(pw1.w);
        *(float4*)&Ws[(sr + 64) * GST + sc] = t;
        __syncthreads();

        int kn = k0 + 16;
        if (kn < K) {
            pa0 = *(const float4*)(Ag + kn);
            pa1 = *(const float4*)(Ag + (size_t)64 * K + kn);
            pw0 = *(const float4*)(Wg + kn);
            pw1 = *(const float4*)(Wg + (size_t)64 * K + kn);
        }

#pragma unroll
        for (int kk = 0; kk < 16; kk += 8) {
            uint32_t af[4][4], bf[4][2];
#pragma unroll
            for (int mi = 0; mi < 4; mi++)
                ldm_x4(af[mi], smem_u32(&As[(wm + mi * 16 + arow) * GST + kk + acol]));
#pragma unroll
            for (int ni = 0; ni < 4; ni++)
                ldm_x2(bf[ni], smem_u32(&Ws[(wn + ni * 8 + brow) * GST + kk + bcol]));
#pragma unroll
            for (int mi = 0; mi < 4; mi++)
#pragma unroll
                for (int ni = 0; ni < 4; ni++)
                    mma_tf32(acc[mi][ni], af[mi], bf[ni]);
        }
        __syncthreads();
        if (kn >= K) break;
        k0 = kn;
    }

    // epilogue
    const int r0 = lane >> 2, c2 = (lane & 3) << 1;
#pragma unroll
    for (int mi = 0; mi < 4; mi++) {
        int row0 = bm + wm + mi * 16 + r0;
#pragma unroll
        for (int ni = 0; ni < 4; ni++) {
            int col = bn + wn + ni * 8 + c2;
            float bv0 = __ldg(&bias[col]), bv1 = __ldg(&bias[col + 1]);
            store_pair(out, mode, s_off, N, row0, col, acc[mi][ni][0] + bv0, acc[mi][ni][1] + bv1);
            store_pair(out, mode, s_off, N, row0 + 8, col, acc[mi][ni][2] + bv0, acc[mi][ni][3] + bv1);
        }
    }
}

// ---------------------------------------------------------------------------
// Flash attention on tensor cores.
// CTA: 128 threads (4 warps), q-tile 64 (16 rows/warp), k-tile 32, Dh=64.
// Q fragments register-resident; K/V staged in smem (tf32); online softmax on
// mma C-fragments; P via per-warp smem -> A fragments; V B-frags via scalar LDS.
// ---------------------------------------------------------------------------
#define KT 32
#define QST 68   // Qs/Ks/Vs row stride (floats)
#define PST 36   // Ps row stride

__global__ __launch_bounds__(128)
void attn_tc(const float* __restrict__ Q, const float* __restrict__ K,
             const float* __restrict__ V, float* __restrict__ AO)
{
    __shared__ float KV[4352];           // union: Qs[64][68]  OR  Ks[32][68] + Vs[32][68]
    __shared__ float Ps[4][16][PST];

    const int tid = threadIdx.x, lane = tid & 31, warp = tid >> 5;
    const int b = blockIdx.z, h = blockIdx.y, q0 = blockIdx.x * 64;

    const float* Qg = Q + ((size_t)(b * HEADS + h) * SQ + q0) * HD;
    const float* Kg = K + (size_t)(b * HEADS + h) * SKTOT * HD;
    const float* Vg = V + (size_t)(b * HEADS + h) * SKTOT * HD;

    // stage Q [64][64] -> KV (stride 68), tf32
#pragma unroll
    for (int j = 0; j < 8; j++) {
        int chunk = tid + j * 128;            // 0..1023 float4 chunks
        int row = chunk >> 4, c4 = (chunk & 15) << 2;
        float4 v = *(const float4*)(Qg + row * HD + c4);
        float4 w;
        w.x = f2tf32f(v.x); w.y = f2tf32f(v.y); w.z = f2tf32f(v.z); w.w = f2tf32f(v.w);
        *(float4*)&KV[row * QST + c4] = w;
    }
    __syncthreads();

    const int arow = (lane < 16) ? lane : lane - 16;
    const int acol = (lane < 16) ? 0 : 4;
    const int l16 = lane & 15;
    const int brow = l16 & 7;
    const int bcol = (l16 >> 3) << 2;

    // Q fragments: m16 (warp's rows) x k8 over Dh=64 -> 8 frags
    uint32_t qf[8][4];
#pragma unroll
    for (int kf = 0; kf < 8; kf++)
        ldm_x4(qf[kf], smem_u32(&KV[(warp * 16 + arow) * QST + kf * 8 + acol]));
    __syncthreads();   // Qs region now reusable for K/V

    float* Ks = KV;
    float* Vs = KV + 32 * QST;

    float O[8][4];
#pragma unroll
    for (int nf = 0; nf < 8; nf++)
#pragma unroll
        for (int v = 0; v < 4; v++) O[nf][v] = 0.f;
    float m0 = -1e30f, m1 = -1e30f, l0 = 0.f, l1 = 0.f;

    const int r0 = lane >> 2, c2 = (lane & 3) << 1;
    const int kq = lane & 3, gq = lane >> 2;

    for (int kt = 0; kt < SKTOT; kt += KT) {
        // stage K,V tiles [32][64] (tf32)
#pragma unroll
        for (int j = 0; j < 4; j++) {
            int chunk = tid + j * 128;        // 0..511
            int row = chunk >> 4, c4 = (chunk & 15) << 2;
            float4 kv4 = *(const float4*)(Kg + (size_t)(kt + row) * HD + c4);
            float4 vv4 = *(const float4*)(Vg + (size_t)(kt + row) * HD + c4);
            float4 w;
            w.x = f2tf32f(kv4.x); w.y = f2tf32f(kv4.y); w.z = f2tf32f(kv4.z); w.w = f2tf32f(kv4.w);
            *(float4*)&Ks[row * QST + c4] = w;
            w.x = f2tf32f(vv4.x); w.y = f2tf32f(vv4.y); w.z = f2tf32f(vv4.z); w.w = f2tf32f(vv4.w);
            *(float4*)&Vs[row * QST + c4] = w;
        }
        __syncthreads();

        // S = Q K^T  (warp: m16 x n32)
        float s[4][4];
#pragma unroll
        for (int nf = 0; nf < 4; nf++)
#pragma unroll
            for (int v = 0; v < 4; v++) s[nf][v] = 0.f;
#pragma unroll
        for (int kf = 0; kf < 8; kf++) {
#pragma unroll
            for (int nf = 0; nf < 4; nf++) {
                uint32_t bf[2];
                ldm_x2(bf, smem_u32(&Ks[(nf * 8 + brow) * QST + kf * 8 + bcol]));
                mma_tf32(s[nf], qf[kf], bf);
            }
        }

        // online softmax (scale 1/8 folded into exp args)
        float mx0 = fmaxf(s[0][0], s[0][1]), mx1 = fmaxf(s[0][2], s[0][3]);
#pragma unroll
        for (int nf = 1; nf < 4; nf++) {
            mx0 = fmaxf(mx0, fmaxf(s[nf][0], s[nf][1]));
            mx1 = fmaxf(mx1, fmaxf(s[nf][2], s[nf][3]));
        }
#pragma unroll
        for (int off = 1; off <= 2; off <<= 1) {
            mx0 = fmaxf(mx0, __shfl_xor_sync(0xffffffffu, mx0, off));
            mx1 = fmaxf(mx1, __shfl_xor_sync(0xffffffffu, mx1, off));
        }
        float nm0 = fmaxf(m0, mx0), nm1 = fmaxf(m1, mx1);
        float corr0 = __expf((m0 - nm0) * 0.125f);
        float corr1 = __expf((m1 - nm1) * 0.125f);
        float rs0 = 0.f, rs1 = 0.f;
#pragma unroll
        for (int nf = 0; nf < 4; nf++) {
            float p0 = __expf((s[nf][0] - nm0) * 0.125f);
            float p1 = __expf((s[nf][1] - nm0) * 0.125f);
            float p2 = __expf((s[nf][2] - nm1) * 0.125f);
            float p3 = __expf((s[nf][3] - nm1) * 0.125f);
            rs0 += p0 + p1; rs1 += p2 + p3;
            *(float2*)&Ps[warp][r0][nf * 8 + c2]     = make_float2(f2tf32f(p0), f2tf32f(p1));
            *(float2*)&Ps[warp][r0 + 8][nf * 8 + c2] = make_float2(f2tf32f(p2), f2tf32f(p3));
        }
#pragma unroll
        for (int off = 1; off <= 2; off <<= 1) {
            rs0 += __shfl_xor_sync(0xffffffffu, rs0, off);
            rs1 += __shfl_xor_sync(0xffffffffu, rs1, off);
        }
        m0 = nm0; m1 = nm1;
        l0 = l0 * corr0 + rs0;
        l1 = l1 * corr1 + rs1;
#pragma unroll
        for (int nf = 0; nf < 8; nf++) {
            O[nf][0] *= corr0; O[nf][1] *= corr0;
            O[nf][2] *= corr1; O[nf][3] *= corr1;
        }
        __syncwarp();

        // O += P V   (m16 x k32 x n64)
#pragma unroll
        for (int ks = 0; ks < 4; ks++) {
            uint32_t pf[4];
            ldm_x4(pf, smem_u32(&Ps[warp][arow][ks * 8 + acol]));
#pragma unroll
            for (int nf = 0; nf < 8; nf++) {
                uint32_t bf[2];
                bf[0] = __float_as_uint(Vs[(ks * 8 + kq) * QST + nf * 8 + gq]);
                bf[1] = __float_as_uint(Vs[(ks * 8 + kq + 4) * QST + nf * 8 + gq]);
                mma_tf32(O[nf], pf, bf);
            }
        }
        __syncthreads();   // PV done before next tile overwrites Ks/Vs
    }

    // write O / l  ->  AO [B*Sq, DIM]
    float i0 = 1.f / l0, i1 = 1.f / l1;
    float* out0 = AO + ((size_t)(b * SQ + q0 + warp * 16 + r0)) * DIMV + h * HD;
    float* out1 = out0 + (size_t)8 * DIMV;
#pragma unroll
    for (int nf = 0; nf < 8; nf++) {
        *(float2*)&out0[nf * 8 + c2] = make_float2(O[nf][0] * i0, O[nf][1] * i0);
        *(float2*)&out1[nf * 8 + c2] = make_float2(O[nf][2] * i1, O[nf][3] * i1);
    }
}

// ---------------------------------------------------------------------------
extern "C" void kernel_launch(void* const* d_in, const int* in_sizes, int n_in,
                              void* d_out, int out_size)
{
    (void)in_sizes; (void)n_in; (void)out_size;
    const float* x     = (const float*)d_in[0];
    const float* y     = (const float*)d_in[1];
    const float* W_Kx  = (const float*)d_in[2];
    const float* b_Kx  = (const float*)d_in[3];
    const float* W_Qx  = (const float*)d_in[4];
    const float* b_Qx  = (const float*)d_in[5];
    const float* W_Vx  = (const float*)d_in[6];
    const float* b_Vx  = (const float*)d_in[7];
    const float* W_Ky  = (const float*)d_in[8];
    const float* b_Ky  = (const float*)d_in[9];
    const float* W_Vy  = (const float*)d_in[10];
    const float* b_Vy  = (const float*)d_in[11];
    const float* W_out = (const float*)d_in[12];
    const float* b_out = (const float*)d_in[13];
    float* out = (float*)d_out;

    void *pQ, *pK, *pV, *pAO;
    cudaGetSymbolAddress(&pQ, g_Q);
    cudaGetSymbolAddress(&pK, g_K);
    cudaGetSymbolAddress(&pV, g_V);
    cudaGetSymbolAddress(&pAO, g_AO);
    float* Qp  = (float*)pQ;
    float* Kp  = (float*)pK;
    float* Vp  = (float*)pV;
    float* AOp = (float*)pAO;

    const int M = BATCH * SQ;   // 4096
    const int N = DIMV;         // 1024
    const int Kd = DIMV;        // 1024
    dim3 gg(N / 128, M / 128);  // (8, 32)

    gemm_tc<<<gg, 256>>>(x, W_Qx, b_Qx, Qp, M, N, Kd, 1, 0);
    gemm_tc<<<gg, 256>>>(x, W_Kx, b_Kx, Kp, M, N, Kd, 2, 0);
    gemm_tc<<<gg, 256>>>(x, W_Vx, b_Vx, Vp, M, N, Kd, 2, 0);
    gemm_tc<<<gg, 256>>>(y, W_Ky, b_Ky, Kp, M, N, Kd, 2, SQ);
    gemm_tc<<<gg, 256>>>(y, W_Vy, b_Vy, Vp, M, N, Kd, 2, SQ);

    attn_tc<<<dim3(SQ / 64, HEADS, BATCH), 128>>>(Qp, Kp, Vp, AOp);

    gemm_tc<<<gg, 256>>>(AOp, W_out, b_out, out, M, N, Kd, 0, 0);
}

// round 4
// speedup vs baseline: 6.4104x; 1.3085x over previous
#include <cuda_runtime.h>
#include <cstdint>

#define DIMV 1024
#define HEADS 16
#define HD 64
#define BATCH 4
#define SQ 1024
#define SKTOT 2048
#define KDIM 1024

// Scratch (allocation-free rule: __device__ globals)
__device__ float g_Q[BATCH * HEADS * SQ * HD];
__device__ float g_K[BATCH * HEADS * SKTOT * HD];
__device__ float g_V[BATCH * HEADS * SKTOT * HD];
__device__ float g_AO[BATCH * SQ * DIMV];
__device__ float g_X[BATCH * SQ * DIMV];      // tf32-rounded x
__device__ float g_Y[BATCH * SQ * DIMV];      // tf32-rounded y
__device__ float g_W6[6 * DIMV * DIMV];       // tf32-rounded weights

// ---------------- helpers ----------------
__device__ __forceinline__ uint32_t f2tf32(float x) {
    uint32_t u; asm("cvt.rna.tf32.f32 %0, %1;" : "=r"(u) : "f"(x)); return u;
}
__device__ __forceinline__ float f2tf32f(float x) { return __uint_as_float(f2tf32(x)); }

__device__ __forceinline__ uint32_t smem_u32(const void* p) {
    return (uint32_t)__cvta_generic_to_shared(p);
}
__device__ __forceinline__ void ldm_x4(uint32_t* r, uint32_t a) {
    asm volatile("ldmatrix.sync.aligned.m8n8.x4.shared.b16 {%0,%1,%2,%3}, [%4];"
                 : "=r"(r[0]), "=r"(r[1]), "=r"(r[2]), "=r"(r[3]) : "r"(a));
}
__device__ __forceinline__ void mma_tf32(float* c, const uint32_t* a, const uint32_t* b) {
    asm volatile(
        "mma.sync.aligned.m16n8k8.row.col.f32.tf32.tf32.f32 "
        "{%0,%1,%2,%3},{%4,%5,%6,%7},{%8,%9},{%0,%1,%2,%3};"
        : "+f"(c[0]), "+f"(c[1]), "+f"(c[2]), "+f"(c[3])
        : "r"(a[0]), "r"(a[1]), "r"(a[2]), "r"(a[3]), "r"(b[0]), "r"(b[1]));
}
#define CP16(dst, src) \
    asm volatile("cp.async.cg.shared.global [%0], [%1], 16;" :: "r"(dst), "l"(src))
#define CP_COMMIT() asm volatile("cp.async.commit_group;" ::)
#define CP_WAIT1()  asm volatile("cp.async.wait_group 1;" ::)
#define CP_WAIT0()  asm volatile("cp.async.wait_group 0;" ::)

// ---------------------------------------------------------------------------
// Pre-pass: round tensors to tf32 (rna) once, so hot loops need no cvt.
// ---------------------------------------------------------------------------
struct RoundArgs { const float* src[8]; float* dst[8]; int n4[8]; };

__global__ __launch_bounds__(256)
void round_tf32_k(RoundArgs ra) {
    int seg = blockIdx.y;
    const float4* s = (const float4*)ra.src[seg];
    float4* d = (float4*)ra.dst[seg];
    int n4 = ra.n4[seg];
    for (int i = blockIdx.x * blockDim.x + threadIdx.x; i < n4; i += gridDim.x * blockDim.x) {
        float4 v = s[i];
        v.x = f2tf32f(v.x); v.y = f2tf32f(v.y);
        v.z = f2tf32f(v.z); v.w = f2tf32f(v.w);
        d[i] = v;
    }
}

// ---------------------------------------------------------------------------
// GEMM: C[M,N] = A[M,1024] @ W[N,1024]^T + bias  (tf32 mma, 128x128 tile,
// 4 warps of 64x64, cp.async double-buffered k-chunks of 16).
// Inputs pre-rounded to tf32. Outputs for modes 1/2 rounded (feed attention).
// ---------------------------------------------------------------------------
#define GST 20

struct ProjArgs {
    const float* A; const float* W; const float* bias; float* out;
    int mode; int s_off;
};
struct Proj5 { ProjArgs p[5]; };

__device__ __forceinline__ void store_pair(float* __restrict__ out, int mode, int s_off,
                                           int row, int col, float v0, float v1) {
    size_t idx;
    if (mode == 0) {
        idx = (size_t)row * DIMV + col;
    } else {
        int b = row >> 10, s = row & 1023, h = col >> 6, d = col & 63;
        int S = (mode == 1) ? SQ : SKTOT;
        idx = ((size_t)(b * HEADS + h) * S + (s + s_off)) * HD + d;
        v0 = f2tf32f(v0);   // round for downstream tf32 mma
        v1 = f2tf32f(v1);
    }
    *(float2*)(out + idx) = make_float2(v0, v1);
}

__device__ __forceinline__ void gemm_body(const float* __restrict__ A,
                                          const float* __restrict__ W,
                                          const float* __restrict__ bias,
                                          float* __restrict__ out,
                                          int mode, int s_off)
{
    __shared__ float As[2][128 * GST];
    __shared__ float Ws[2][128 * GST];

    const int tid = threadIdx.x, lane = tid & 31, warp = tid >> 5;
    const int wm = (warp >> 1) << 6, wn = (warp & 1) << 6;
    const int bm = blockIdx.y << 7, bn = blockIdx.x << 7;

    const int r0s = tid >> 2, c4s = (tid & 3) << 2;
    const float* Ag = A + (size_t)(bm + r0s) * KDIM + c4s;
    const float* Wg = W + (size_t)(bn + r0s) * KDIM + c4s;

    float acc[4][8][4];
#pragma unroll
    for (int i = 0; i < 4; i++)
#pragma unroll
        for (int j = 0; j < 8; j++)
#pragma unroll
            for (int v = 0; v < 4; v++) acc[i][j][v] = 0.f;

    const int arow = lane & 15, acol = (lane >> 4) << 2;
    const int within = lane & 15;
    const int brow = within & 7, bcol = (within >> 3) << 2;
    const int g8 = (lane >> 4) << 3;

#define STAGE_G(buf, k0) do { \
    _Pragma("unroll") \
    for (int j = 0; j < 4; j++) { \
        CP16(smem_u32(&As[buf][(r0s + 32 * j) * GST + c4s]), Ag + (size_t)32 * j * KDIM + (k0)); \
        CP16(smem_u32(&Ws[buf][(r0s + 32 * j) * GST + c4s]), Wg + (size_t)32 * j * KDIM + (k0)); \
    } \
    CP_COMMIT(); \
} while (0)

    STAGE_G(0, 0);

    for (int c = 0; c < KDIM / 16; c++) {
        int kn = (c + 1) * 16;
        if (kn < KDIM) { STAGE_G((c + 1) & 1, kn); CP_WAIT1(); }
        else           { CP_WAIT0(); }
        __syncthreads();

        const float* as = As[c & 1];
        const float* ws = Ws[c & 1];
#pragma unroll
        for (int kk = 0; kk < 16; kk += 8) {
            uint32_t af[4][4];
#pragma unroll
            for (int mi = 0; mi < 4; mi++)
                ldm_x4(af[mi], smem_u32(&as[(wm + mi * 16 + arow) * GST + kk + acol]));
            uint32_t bf[8][2];
#pragma unroll
            for (int nn = 0; nn < 4; nn++) {
                uint32_t r[4];
                ldm_x4(r, smem_u32(&ws[(wn + nn * 16 + g8 + brow) * GST + kk + bcol]));
                bf[2 * nn][0] = r[0]; bf[2 * nn][1] = r[1];
                bf[2 * nn + 1][0] = r[2]; bf[2 * nn + 1][1] = r[3];
            }
#pragma unroll
            for (int mi = 0; mi < 4; mi++)
#pragma unroll
                for (int ni = 0; ni < 8; ni++)
                    mma_tf32(acc[mi][ni], af[mi], bf[ni]);
        }
        __syncthreads();
    }

    const int r0 = lane >> 2, c2 = (lane & 3) << 1;
#pragma unroll
    for (int mi = 0; mi < 4; mi++) {
        int row0 = bm + wm + mi * 16 + r0;
#pragma unroll
        for (int ni = 0; ni < 8; ni++) {
            int col = bn + wn + ni * 8 + c2;
            float2 bv = *(const float2*)&bias[col];
            store_pair(out, mode, s_off, row0, col, acc[mi][ni][0] + bv.x, acc[mi][ni][1] + bv.y);
            store_pair(out, mode, s_off, row0 + 8, col, acc[mi][ni][2] + bv.x, acc[mi][ni][3] + bv.y);
        }
    }
}

__global__ __launch_bounds__(128)
void proj5_tc(Proj5 all) {
    ProjArgs a = all.p[blockIdx.z];
    gemm_body(a.A, a.W, a.bias, a.out, a.mode, a.s_off);
}
__global__ __launch_bounds__(128)
void gemm1_tc(ProjArgs a) {
    gemm_body(a.A, a.W, a.bias, a.out, a.mode, a.s_off);
}

// ---------------------------------------------------------------------------
// Flash attention (tf32 mma): 4 warps, q-tile 64 (16/warp), k-tile 64, Dh=64.
// Q/K/V pre-rounded tf32; P rounded before Ps store; AO rounded at write-out.
// ---------------------------------------------------------------------------
#define KT 64
#define QST 68
#define PST 36

__global__ __launch_bounds__(128)
void attn_tc(const float* __restrict__ Q, const float* __restrict__ K,
             const float* __restrict__ V, float* __restrict__ AO)
{
    __shared__ float Ks[64 * QST];
    __shared__ float Vs[64 * QST];
    __shared__ float Ps[4][16 * PST];

    const int tid = threadIdx.x, lane = tid & 31, warp = tid >> 5;
    const int b = blockIdx.z, h = blockIdx.y, q0 = blockIdx.x * 64;

    const float* Qg = Q + ((size_t)(b * HEADS + h) * SQ + q0) * HD;
    const float* Kg = K + (size_t)(b * HEADS + h) * SKTOT * HD;
    const float* Vg = V + (size_t)(b * HEADS + h) * SKTOT * HD;

    const int arow = lane & 15, acol = (lane >> 4) << 2;
    const int within = lane & 15;
    const int brow = within & 7, bcol = (within >> 3) << 2;
    const int g8 = (lane >> 4) << 3;
    const int r0 = lane >> 2, c2 = (lane & 3) << 1;
    const int kq = lane & 3, gq = lane >> 2;

    // stage Q [64][64] into Ks
#pragma unroll
    for (int j = 0; j < 8; j++) {
        int chunk = tid + 128 * j;
        int row = chunk >> 4, c4 = (chunk & 15) << 2;
        CP16(smem_u32(&Ks[row * QST + c4]), Qg + (size_t)row * HD + c4);
    }
    CP_COMMIT(); CP_WAIT0();
    __syncthreads();

    uint32_t qf[8][4];
#pragma unroll
    for (int kf = 0; kf < 8; kf++)
        ldm_x4(qf[kf], smem_u32(&Ks[(warp * 16 + arow) * QST + kf * 8 + acol]));
    __syncthreads();

    float O[8][4];
#pragma unroll
    for (int nf = 0; nf < 8; nf++)
#pragma unroll
        for (int v = 0; v < 4; v++) O[nf][v] = 0.f;
    float m0 = -1e30f, m1 = -1e30f, l0 = 0.f, l1 = 0.f;

    for (int kt = 0; kt < SKTOT; kt += KT) {
        // stage K,V tiles [64][64]
#pragma unroll
        for (int j = 0; j < 8; j++) {
            int chunk = tid + 128 * j;
            int row = chunk >> 4, c4 = (chunk & 15) << 2;
            CP16(smem_u32(&Ks[row * QST + c4]), Kg + (size_t)(kt + row) * HD + c4);
            CP16(smem_u32(&Vs[row * QST + c4]), Vg + (size_t)(kt + row) * HD + c4);
        }
        CP_COMMIT(); CP_WAIT0();
        __syncthreads();

        // S = Q K^T : m16 x n64
        float s[8][4];
#pragma unroll
        for (int nf = 0; nf < 8; nf++)
#pragma unroll
            for (int v = 0; v < 4; v++) s[nf][v] = 0.f;
#pragma unroll
        for (int kf = 0; kf < 8; kf++) {
#pragma unroll
            for (int nn = 0; nn < 4; nn++) {
                uint32_t r[4];
                ldm_x4(r, smem_u32(&Ks[(nn * 16 + g8 + brow) * QST + kf * 8 + bcol]));
                uint32_t b0[2] = { r[0], r[1] }, b1[2] = { r[2], r[3] };
                mma_tf32(s[2 * nn], qf[kf], b0);
                mma_tf32(s[2 * nn + 1], qf[kf], b1);
            }
        }

        // online softmax (scale 1/8 folded into exp args)
        float mx0 = fmaxf(s[0][0], s[0][1]), mx1 = fmaxf(s[0][2], s[0][3]);
#pragma unroll
        for (int nf = 1; nf < 8; nf++) {
            mx0 = fmaxf(mx0, fmaxf(s[nf][0], s[nf][1]));
            mx1 = fmaxf(mx1, fmaxf(s[nf][2], s[nf][3]));
        }
#pragma unroll
        for (int off = 1; off <= 2; off <<= 1) {
            mx0 = fmaxf(mx0, __shfl_xor_sync(0xffffffffu, mx0, off));
            mx1 = fmaxf(mx1, __shfl_xor_sync(0xffffffffu, mx1, off));
        }
        float nm0 = fmaxf(m0, mx0), nm1 = fmaxf(m1, mx1);
        float corr0 = __expf((m0 - nm0) * 0.125f);
        float corr1 = __expf((m1 - nm1) * 0.125f);
        m0 = nm0; m1 = nm1;
#pragma unroll
        for (int nf = 0; nf < 8; nf++) {
            O[nf][0] *= corr0; O[nf][1] *= corr0;
            O[nf][2] *= corr1; O[nf][3] *= corr1;
        }
        float rs0 = 0.f, rs1 = 0.f;

        // PV in two 32-k halves
#pragma unroll
        for (int hh = 0; hh < 2; hh++) {
#pragma unroll
            for (int nf = 0; nf < 4; nf++) {
                float p0 = __expf((s[4 * hh + nf][0] - nm0) * 0.125f);
                float p1 = __expf((s[4 * hh + nf][1] - nm0) * 0.125f);
                float p2 = __expf((s[4 * hh + nf][2] - nm1) * 0.125f);
                float p3 = __expf((s[4 * hh + nf][3] - nm1) * 0.125f);
                rs0 += p0 + p1; rs1 += p2 + p3;
                *(float2*)&Ps[warp][r0 * PST + nf * 8 + c2] =
                    make_float2(f2tf32f(p0), f2tf32f(p1));
                *(float2*)&Ps[warp][(r0 + 8) * PST + nf * 8 + c2] =
                    make_float2(f2tf32f(p2), f2tf32f(p3));
            }
            __syncwarp();
#pragma unroll
            for (int ks = 0; ks < 4; ks++) {
                uint32_t pf[4];
                ldm_x4(pf, smem_u32(&Ps[warp][arow * PST + ks * 8 + acol]));
                const float* vrow = &Vs[(hh * 32 + ks * 8 + kq) * QST + gq];
#pragma unroll
                for (int nf = 0; nf < 8; nf++) {
                    uint32_t bfv[2];
                    bfv[0] = __float_as_uint(vrow[nf * 8]);
                    bfv[1] = __float_as_uint(vrow[4 * QST + nf * 8]);
                    mma_tf32(O[nf], pf, bfv);
                }
            }
            __syncwarp();
        }
#pragma unroll
        for (int off = 1; off <= 2; off <<= 1) {
            rs0 += __shfl_xor_sync(0xffffffffu, rs0, off);
            rs1 += __shfl_xor_sync(0xffffffffu, rs1, off);
        }
        l0 = l0 * corr0 + rs0;
        l1 = l1 * corr1 + rs1;
        __syncthreads();
    }

    // AO rounded to tf32 (feeds the output-projection mma)
    float i0 = 1.f / l0, i1 = 1.f / l1;
    float* out0 = AO + ((size_t)(b * SQ + q0 + warp * 16 + r0)) * DIMV + h * HD;
    float* out1 = out0 + (size_t)8 * DIMV;
#pragma unroll
    for (int nf = 0; nf < 8; nf++) {
        *(float2*)&out0[nf * 8 + c2] =
            make_float2(f2tf32f(O[nf][0] * i0), f2tf32f(O[nf][1] * i0));
        *(float2*)&out1[nf * 8 + c2] =
            make_float2(f2tf32f(O[nf][2] * i1), f2tf32f(O[nf][3] * i1));
    }
}

// ---------------------------------------------------------------------------
extern "C" void kernel_launch(void* const* d_in, const int* in_sizes, int n_in,
                              void* d_out, int out_size)
{
    (void)in_sizes; (void)n_in; (void)out_size;
    const float* x     = (const float*)d_in[0];
    const float* y     = (const float*)d_in[1];
    const float* W_Kx  = (const float*)d_in[2];
    const float* b_Kx  = (const float*)d_in[3];
    const float* W_Qx  = (const float*)d_in[4];
    const float* b_Qx  = (const float*)d_in[5];
    const float* W_Vx  = (const float*)d_in[6];
    const float* b_Vx  = (const float*)d_in[7];
    const float* W_Ky  = (const float*)d_in[8];
    const float* b_Ky  = (const float*)d_in[9];
    const float* W_Vy  = (const float*)d_in[10];
    const float* b_Vy  = (const float*)d_in[11];
    const float* W_out = (const float*)d_in[12];
    const float* b_out = (const float*)d_in[13];
    float* out = (float*)d_out;

    void *pQ, *pK, *pV, *pAO, *pX, *pY, *pW;
    cudaGetSymbolAddress(&pQ, g_Q);
    cudaGetSymbolAddress(&pK, g_K);
    cudaGetSymbolAddress(&pV, g_V);
    cudaGetSymbolAddress(&pAO, g_AO);
    cudaGetSymbolAddress(&pX, g_X);
    cudaGetSymbolAddress(&pY, g_Y);
    cudaGetSymbolAddress(&pW, g_W6);
    float* Qp  = (float*)pQ;
    float* Kp  = (float*)pK;
    float* Vp  = (float*)pV;
    float* AOp = (float*)pAO;
    float* Xp  = (float*)pX;
    float* Yp  = (float*)pY;
    float* Wp  = (float*)pW;

    const int NW = DIMV * DIMV;          // 1M floats per weight
    const int NX = BATCH * SQ * DIMV;    // 4M floats

    // Pre-pass: round x, y, and the 6 weight matrices to tf32 (rna)
    RoundArgs ra;
    ra.src[0] = x;     ra.dst[0] = Xp;          ra.n4[0] = NX / 4;
    ra.src[1] = y;     ra.dst[1] = Yp;          ra.n4[1] = NX / 4;
    ra.src[2] = W_Qx;  ra.dst[2] = Wp + 0 * NW; ra.n4[2] = NW / 4;
    ra.src[3] = W_Kx;  ra.dst[3] = Wp + 1 * NW; ra.n4[3] = NW / 4;
    ra.src[4] = W_Vx;  ra.dst[4] = Wp + 2 * NW; ra.n4[4] = NW / 4;
    ra.src[5] = W_Ky;  ra.dst[5] = Wp + 3 * NW; ra.n4[5] = NW / 4;
    ra.src[6] = W_Vy;  ra.dst[6] = Wp + 4 * NW; ra.n4[6] = NW / 4;
    ra.src[7] = W_out; ra.dst[7] = Wp + 5 * NW; ra.n4[7] = NW / 4;
    round_tf32_k<<<dim3(512, 8), 256>>>(ra);

    Proj5 pj;
    pj.p[0] = { Xp, Wp + 0 * NW, b_Qx, Qp, 1, 0 };
    pj.p[1] = { Xp, Wp + 1 * NW, b_Kx, Kp, 2, 0 };
    pj.p[2] = { Xp, Wp + 2 * NW, b_Vx, Vp, 2, 0 };
    pj.p[3] = { Yp, Wp + 3 * NW, b_Ky, Kp, 2, SQ };
    pj.p[4] = { Yp, Wp + 4 * NW, b_Vy, Vp, 2, SQ };

    proj5_tc<<<dim3(8, 32, 5), 128>>>(pj);
    attn_tc<<<dim3(SQ / 64, HEADS, BATCH), 128>>>(Qp, Kp, Vp, AOp);
    gemm1_tc<<<dim3(8, 32), 128>>>(ProjArgs{ AOp, Wp + 5 * NW, b_out, out, 0, 0 });
}